// round 9
// baseline (speedup 1.0000x reference)
#include <cuda_runtime.h>
#include <cstdint>
#include <cstddef>

// ---------------------------------------------------------------------------
// FeatureFusionKAN:
//   attention = sigmoid([f1|f2] @ attn_w^T + b)            GEMM1 (K=2048)
//   kan_in    = [f1*att | f2*(1-att)]
//   h     = [silu(kan_in)|bspl(kan_in)] @ W0 (K=18432)     GEMM2
//   out   = [silu(h)     |bspl(h)    ] @ W1 (K=9216)       GEMM3
// All GEMMs: M=8192, N=1024. TF32 mma.sync with RNA-rounded operands,
// fp32 accumulate.
// ---------------------------------------------------------------------------

#define BATCH   8192
#define FEATN   1024
#define KATTN   2048
#define KL0     18432
#define KL1     9216

// ------------------------- device scratch (no allocs) ----------------------
__device__ float g_Acomb [(size_t)BATCH * KATTN];   //  64 MB
__device__ float g_Wattn [(size_t)FEATN * KATTN];   //   8 MB
__device__ float g_logits[(size_t)BATCH * FEATN];   //  32 MB
__device__ float g_W0    [(size_t)FEATN * KL0];     //  72 MB
__device__ float g_Xe0   [(size_t)BATCH * KL0];     // 576 MB
__device__ float g_h     [(size_t)BATCH * FEATN];   //  32 MB
__device__ float g_W1    [(size_t)FEATN * KL1];     //  36 MB
__device__ float g_Xe1   [(size_t)BATCH * KL1];     // 288 MB

// ------------------------------ helpers ------------------------------------
__device__ __forceinline__ float rna_tf32(float f) {
    uint32_t u;
    asm("cvt.rna.tf32.f32 %0, %1;" : "=r"(u) : "f"(f));
    return __uint_as_float(u);
}

__device__ __forceinline__ float sigmoidf_(float z) {
    return 1.0f / (1.0f + expf(-z));
}

// Cox-de Boor, order 3, uniform extended grid g_j = -1 + (j-3)*0.4, j=0..11.
// Produces the 8 cubic basis values. Matches the reference recursion.
__device__ __forceinline__ void bspline8(float x, float bb[8]) {
    const float h = 0.4f;
    float b[11];
#pragma unroll
    for (int j = 0; j < 11; ++j) {
        float g0 = -1.0f + (float)(j - 3) * h;
        float g1 = -1.0f + (float)(j - 2) * h;
        b[j] = (x >= g0 && x < g1) ? 1.0f : 0.0f;
    }
#pragma unroll
    for (int k = 1; k <= 3; ++k) {
        float invkh = 1.0f / ((float)k * h);
#pragma unroll
        for (int j = 0; j < 11 - k; ++j) {
            float gj   = -1.0f + (float)(j - 3) * h;
            float gjk1 = -1.0f + (float)(j + k - 2) * h;
            float left  = (x - gj)   * invkh;
            float right = (gjk1 - x) * invkh;
            b[j] = left * b[j] + right * b[j + 1];
        }
    }
#pragma unroll
    for (int i = 0; i < 8; ++i) bb[i] = b[i];
}

// ------------------------------ prep kernels -------------------------------
// A for attention GEMM: [f1|f2] RNA-rounded. 8192 x 2048.
__global__ void k_concat_round(const float* __restrict__ f1,
                               const float* __restrict__ f2,
                               float* __restrict__ dst) {
    int idx = blockIdx.x * blockDim.x + threadIdx.x;
    if (idx >= BATCH * KATTN) return;
    int b = idx >> 11;           // /2048
    int j = idx & 2047;
    float v = (j < FEATN) ? f1[b * FEATN + j] : f2[b * FEATN + (j - FEATN)];
    dst[idx] = rna_tf32(v);
}

__global__ void k_round_copy(const float* __restrict__ src,
                             float* __restrict__ dst, int n) {
    int idx = blockIdx.x * blockDim.x + threadIdx.x;
    if (idx < n) dst[idx] = rna_tf32(src[idx]);
}

// Assemble W = [base_w ; spline_w reshaped], layout [N][Ktot] (K contiguous),
// RNA-rounded. spline_w is (N, in, 8) row-major so the (in*8) tail is already
// contiguous per output row.
__global__ void k_pack_w(const float* __restrict__ basew,
                         const float* __restrict__ splinew,
                         float* __restrict__ dst,
                         int kbase, int ktot) {
    int idx = blockIdx.x * blockDim.x + threadIdx.x;
    int total = FEATN * ktot;
    if (idx >= total) return;
    int n = idx / ktot;
    int k = idx - n * ktot;
    float v = (k < kbase) ? basew[(size_t)n * kbase + k]
                          : splinew[(size_t)n * (ktot - kbase) + (k - kbase)];
    dst[idx] = rna_tf32(v);
}

// Expansion for layer 0: consumes attn logits, emits Xe0 row =
// [ silu(kan_in)[0..2047] | for i: B_0..B_7(kan_in[i]) ]  (18432 floats).
__global__ void k_build_xe0(const float* __restrict__ f1,
                            const float* __restrict__ f2,
                            const float* __restrict__ logits,
                            const float* __restrict__ bias,
                            float* __restrict__ xe) {
    int b = blockIdx.y;
    int j = blockIdx.x * blockDim.x + threadIdx.x;  // 0..2047
    if (j >= KATTN) return;
    int f = j & (FEATN - 1);
    float att = sigmoidf_(logits[(size_t)b * FEATN + f] + bias[f]);
    float x = (j < FEATN) ? f1[(size_t)b * FEATN + j] * att
                          : f2[(size_t)b * FEATN + f] * (1.0f - att);
    size_t base = (size_t)b * KL0;
    xe[base + j] = rna_tf32(x * sigmoidf_(x));   // silu
    float bb[8];
    bspline8(x, bb);
    float4 v0 = make_float4(rna_tf32(bb[0]), rna_tf32(bb[1]),
                            rna_tf32(bb[2]), rna_tf32(bb[3]));
    float4 v1 = make_float4(rna_tf32(bb[4]), rna_tf32(bb[5]),
                            rna_tf32(bb[6]), rna_tf32(bb[7]));
    float4* p = (float4*)(xe + base + KATTN + (size_t)j * 8);
    p[0] = v0;
    p[1] = v1;
}

// Expansion for layer 1 (in = 1024, Ktot = 9216).
__global__ void k_build_xe1(const float* __restrict__ h,
                            float* __restrict__ xe) {
    int b = blockIdx.y;
    int j = blockIdx.x * blockDim.x + threadIdx.x;  // 0..1023
    if (j >= FEATN) return;
    float x = h[(size_t)b * FEATN + j];
    size_t base = (size_t)b * KL1;
    xe[base + j] = rna_tf32(x * sigmoidf_(x));
    float bb[8];
    bspline8(x, bb);
    float4 v0 = make_float4(rna_tf32(bb[0]), rna_tf32(bb[1]),
                            rna_tf32(bb[2]), rna_tf32(bb[3]));
    float4 v1 = make_float4(rna_tf32(bb[4]), rna_tf32(bb[5]),
                            rna_tf32(bb[6]), rna_tf32(bb[7]));
    float4* p = (float4*)(xe + base + FEATN + (size_t)j * 8);
    p[0] = v0;
    p[1] = v1;
}

// ------------------------------- GEMM --------------------------------------
// C[M,N] = A[M,K] (row-major) * B^T where B stored [N][K] (K contiguous).
// TF32 mma.sync m16n8k8, fp32 accumulate. CTA tile 128x128, BK=16,
// 8 warps (4x2), warp tile 32x64. 2-stage cp.async pipeline.
#define GT_M 128
#define GT_N 128
#define GT_K 16
#define GSTRIDE 20   // BK + 4 pad -> conflict-free LDS, rows stay 16B aligned

__device__ __forceinline__ void cp_async16(void* smem, const void* gmem) {
    uint32_t s = (uint32_t)__cvta_generic_to_shared(smem);
    asm volatile("cp.async.cg.shared.global [%0], [%1], 16;\n" ::
                 "r"(s), "l"(gmem));
}

__device__ __forceinline__ void mma_tf32(float c[4], const uint32_t a[4],
                                         const uint32_t b[2]) {
    asm volatile(
        "mma.sync.aligned.m16n8k8.row.col.f32.tf32.tf32.f32 "
        "{%0,%1,%2,%3}, {%4,%5,%6,%7}, {%8,%9}, {%0,%1,%2,%3};\n"
        : "+f"(c[0]), "+f"(c[1]), "+f"(c[2]), "+f"(c[3])
        : "r"(a[0]), "r"(a[1]), "r"(a[2]), "r"(a[3]),
          "r"(b[0]), "r"(b[1]));
}

__global__ void __launch_bounds__(256, 2)
k_gemm_tf32(const float* __restrict__ A, const float* __restrict__ B,
            float* __restrict__ C, int M, int N, int K) {
    __shared__ __align__(16) float As[2][GT_M][GSTRIDE];
    __shared__ __align__(16) float Bs[2][GT_N][GSTRIDE];

    const int tid  = threadIdx.x;
    const int lane = tid & 31;
    const int wid  = tid >> 5;
    const int wm   = wid & 3;   // warp row   (0..3) -> 32 M-rows each
    const int wn   = wid >> 2;  // warp col   (0..1) -> 64 N-cols each
    const int g    = lane >> 2; // group id 0..7
    const int t4   = lane & 3;  // thread-in-group 0..3

    const int mBase = blockIdx.y * GT_M;
    const int nBase = blockIdx.x * GT_N;

    // loader mapping: 512 float4 per tile, 2 per thread (rows r and r+64)
    const int ldRow = tid >> 2;          // 0..63
    const int ldC4  = (tid & 3) * 4;     // 0,4,8,12
    const float* Aptr = A + (size_t)(mBase + ldRow) * K + ldC4;
    const float* Bptr = B + (size_t)(nBase + ldRow) * K + ldC4;

    float acc[2][8][4];
#pragma unroll
    for (int mt = 0; mt < 2; ++mt)
#pragma unroll
        for (int nt = 0; nt < 8; ++nt)
#pragma unroll
            for (int i = 0; i < 4; ++i) acc[mt][nt][i] = 0.0f;

    const int numK = K / GT_K;

    // prologue: stage 0
    cp_async16(&As[0][ldRow][ldC4],      Aptr);
    cp_async16(&As[0][ldRow + 64][ldC4], Aptr + (size_t)64 * K);
    cp_async16(&Bs[0][ldRow][ldC4],      Bptr);
    cp_async16(&Bs[0][ldRow + 64][ldC4], Bptr + (size_t)64 * K);
    asm volatile("cp.async.commit_group;\n");

    for (int kt = 0; kt < numK; ++kt) {
        asm volatile("cp.async.wait_group 0;\n");
        __syncthreads();
        const int st = kt & 1;

        if (kt + 1 < numK) {
            const int ns = st ^ 1;
            const int ko = (kt + 1) * GT_K;
            cp_async16(&As[ns][ldRow][ldC4],      Aptr + ko);
            cp_async16(&As[ns][ldRow + 64][ldC4], Aptr + (size_t)64 * K + ko);
            cp_async16(&Bs[ns][ldRow][ldC4],      Bptr + ko);
            cp_async16(&Bs[ns][ldRow + 64][ldC4], Bptr + (size_t)64 * K + ko);
            asm volatile("cp.async.commit_group;\n");
        }

#pragma unroll
        for (int kk = 0; kk < GT_K; kk += 8) {
            uint32_t a[2][4];
#pragma unroll
            for (int mt = 0; mt < 2; ++mt) {
                const int r = wm * 32 + mt * 16;
                a[mt][0] = __float_as_uint(As[st][r + g][kk + t4]);
                a[mt][1] = __float_as_uint(As[st][r + g + 8][kk + t4]);
                a[mt][2] = __float_as_uint(As[st][r + g][kk + t4 + 4]);
                a[mt][3] = __float_as_uint(As[st][r + g + 8][kk + t4 + 4]);
            }
            uint32_t b[8][2];
#pragma unroll
            for (int nt = 0; nt < 8; ++nt) {
                const int c = wn * 64 + nt * 8;
                b[nt][0] = __float_as_uint(Bs[st][c + g][kk + t4]);
                b[nt][1] = __float_as_uint(Bs[st][c + g][kk + t4 + 4]);
            }
#pragma unroll
            for (int mt = 0; mt < 2; ++mt)
#pragma unroll
                for (int nt = 0; nt < 8; ++nt)
                    mma_tf32(acc[mt][nt], a[mt], b[nt]);
        }
        __syncthreads();
    }

    // epilogue
#pragma unroll
    for (int mt = 0; mt < 2; ++mt) {
#pragma unroll
        for (int nt = 0; nt < 8; ++nt) {
            const int r = mBase + wm * 32 + mt * 16 + g;
            const int c = nBase + wn * 64 + nt * 8 + 2 * t4;
            float2* p0 = (float2*)(C + (size_t)r * N + c);
            *p0 = make_float2(acc[mt][nt][0], acc[mt][nt][1]);
            float2* p1 = (float2*)(C + (size_t)(r + 8) * N + c);
            *p1 = make_float2(acc[mt][nt][2], acc[mt][nt][3]);
        }
    }
}

// ------------------------------ launch --------------------------------------
extern "C" void kernel_launch(void* const* d_in, const int* in_sizes, int n_in,
                              void* d_out, int out_size) {
    const float* feat1     = (const float*)d_in[0];
    const float* feat2     = (const float*)d_in[1];
    const float* attn_w    = (const float*)d_in[2];
    const float* attn_b    = (const float*)d_in[3];
    const float* base_w0   = (const float*)d_in[4];
    const float* spline_w0 = (const float*)d_in[5];
    const float* base_w1   = (const float*)d_in[6];
    const float* spline_w1 = (const float*)d_in[7];
    float* out = (float*)d_out;

    float *Acomb, *Wattn, *logits, *W0, *Xe0, *h, *W1, *Xe1;
    cudaGetSymbolAddress((void**)&Acomb,  g_Acomb);
    cudaGetSymbolAddress((void**)&Wattn,  g_Wattn);
    cudaGetSymbolAddress((void**)&logits, g_logits);
    cudaGetSymbolAddress((void**)&W0,     g_W0);
    cudaGetSymbolAddress((void**)&Xe0,    g_Xe0);
    cudaGetSymbolAddress((void**)&h,      g_h);
    cudaGetSymbolAddress((void**)&W1,     g_W1);
    cudaGetSymbolAddress((void**)&Xe1,    g_Xe1);

    const dim3 gemmGrid(FEATN / GT_N, BATCH / GT_M);  // (8, 64)

    // weight prep (independent of activations)
    {
        int n = FEATN * KATTN;
        k_round_copy<<<(n + 255) / 256, 256>>>(attn_w, Wattn, n);
    }
    {
        int n = FEATN * KL0;
        k_pack_w<<<(n + 255) / 256, 256>>>(base_w0, spline_w0, W0, KATTN, KL0);
    }
    {
        int n = FEATN * KL1;
        k_pack_w<<<(n + 255) / 256, 256>>>(base_w1, spline_w1, W1, FEATN, KL1);
    }

    // attention GEMM
    {
        int n = BATCH * KATTN;
        k_concat_round<<<(n + 255) / 256, 256>>>(feat1, feat2, Acomb);
    }
    k_gemm_tf32<<<gemmGrid, 256>>>(Acomb, Wattn, logits, BATCH, FEATN, KATTN);

    // layer 0
    k_build_xe0<<<dim3(KATTN / 256, BATCH), 256>>>(feat1, feat2, logits,
                                                   attn_b, Xe0);
    k_gemm_tf32<<<gemmGrid, 256>>>(Xe0, W0, h, BATCH, FEATN, KL0);

    // layer 1
    k_build_xe1<<<dim3(FEATN / 256, BATCH), 256>>>(h, Xe1);
    k_gemm_tf32<<<gemmGrid, 256>>>(Xe1, W1, out, BATCH, FEATN, KL1);
}

// round 10
// speedup vs baseline: 1.0051x; 1.0051x over previous
#include <cuda_runtime.h>
#include <cstdint>
#include <cstddef>

// ---------------------------------------------------------------------------
// FeatureFusionKAN:
//   attention = sigmoid([f1|f2] @ attn_w^T + b)            GEMM1 (K=2048)
//   kan_in    = [f1*att | f2*(1-att)]
//   h     = [silu(kan_in)|bspl(kan_in)] @ W0 (K=18432)     GEMM2
//   out   = [silu(h)     |bspl(h)    ] @ W1 (K=9216)       GEMM3
// All GEMMs: M=8192, N=1024. TF32 mma.sync with RNA-rounded operands,
// fp32 accumulate.
// ---------------------------------------------------------------------------

#define BATCH   8192
#define FEATN   1024
#define KATTN   2048
#define KL0     18432
#define KL1     9216

// ------------------------- device scratch (no allocs) ----------------------
__device__ float g_Acomb [(size_t)BATCH * KATTN];   //  64 MB
__device__ float g_Wattn [(size_t)FEATN * KATTN];   //   8 MB
__device__ float g_logits[(size_t)BATCH * FEATN];   //  32 MB
__device__ float g_W0    [(size_t)FEATN * KL0];     //  72 MB
__device__ float g_Xe0   [(size_t)BATCH * KL0];     // 576 MB
__device__ float g_h     [(size_t)BATCH * FEATN];   //  32 MB
__device__ float g_W1    [(size_t)FEATN * KL1];     //  36 MB
__device__ float g_Xe1   [(size_t)BATCH * KL1];     // 288 MB

// ------------------------------ helpers ------------------------------------
__device__ __forceinline__ float rna_tf32(float f) {
    uint32_t u;
    asm("cvt.rna.tf32.f32 %0, %1;" : "=r"(u) : "f"(f));
    return __uint_as_float(u);
}

__device__ __forceinline__ float sigmoidf_(float z) {
    return 1.0f / (1.0f + expf(-z));
}

// Cox-de Boor, order 3, uniform extended grid g_j = -1 + (j-3)*0.4, j=0..11.
// Produces the 8 cubic basis values. Matches the reference recursion.
__device__ __forceinline__ void bspline8(float x, float bb[8]) {
    const float h = 0.4f;
    float b[11];
#pragma unroll
    for (int j = 0; j < 11; ++j) {
        float g0 = -1.0f + (float)(j - 3) * h;
        float g1 = -1.0f + (float)(j - 2) * h;
        b[j] = (x >= g0 && x < g1) ? 1.0f : 0.0f;
    }
#pragma unroll
    for (int k = 1; k <= 3; ++k) {
        float invkh = 1.0f / ((float)k * h);
#pragma unroll
        for (int j = 0; j < 11 - k; ++j) {
            float gj   = -1.0f + (float)(j - 3) * h;
            float gjk1 = -1.0f + (float)(j + k - 2) * h;
            float left  = (x - gj)   * invkh;
            float right = (gjk1 - x) * invkh;
            b[j] = left * b[j] + right * b[j + 1];
        }
    }
#pragma unroll
    for (int i = 0; i < 8; ++i) bb[i] = b[i];
}

// ------------------------------ prep kernels -------------------------------
// A for attention GEMM: [f1|f2] RNA-rounded. 8192 x 2048.
__global__ void k_concat_round(const float* __restrict__ f1,
                               const float* __restrict__ f2,
                               float* __restrict__ dst) {
    int idx = blockIdx.x * blockDim.x + threadIdx.x;
    if (idx >= BATCH * KATTN) return;
    int b = idx >> 11;           // /2048
    int j = idx & 2047;
    float v = (j < FEATN) ? f1[b * FEATN + j] : f2[b * FEATN + (j - FEATN)];
    dst[idx] = rna_tf32(v);
}

__global__ void k_round_copy(const float* __restrict__ src,
                             float* __restrict__ dst, int n) {
    int idx = blockIdx.x * blockDim.x + threadIdx.x;
    if (idx < n) dst[idx] = rna_tf32(src[idx]);
}

// Assemble W = [base_w ; spline_w reshaped], layout [N][Ktot] (K contiguous),
// RNA-rounded. spline_w is (N, in, 8) row-major so the (in*8) tail is already
// contiguous per output row.
__global__ void k_pack_w(const float* __restrict__ basew,
                         const float* __restrict__ splinew,
                         float* __restrict__ dst,
                         int kbase, int ktot) {
    int idx = blockIdx.x * blockDim.x + threadIdx.x;
    int total = FEATN * ktot;
    if (idx >= total) return;
    int n = idx / ktot;
    int k = idx - n * ktot;
    float v = (k < kbase) ? basew[(size_t)n * kbase + k]
                          : splinew[(size_t)n * (ktot - kbase) + (k - kbase)];
    dst[idx] = rna_tf32(v);
}

// Expansion for layer 0: consumes attn logits, emits Xe0 row =
// [ silu(kan_in)[0..2047] | for i: B_0..B_7(kan_in[i]) ]  (18432 floats).
__global__ void k_build_xe0(const float* __restrict__ f1,
                            const float* __restrict__ f2,
                            const float* __restrict__ logits,
                            const float* __restrict__ bias,
                            float* __restrict__ xe) {
    int b = blockIdx.y;
    int j = blockIdx.x * blockDim.x + threadIdx.x;  // 0..2047
    if (j >= KATTN) return;
    int f = j & (FEATN - 1);
    float att = sigmoidf_(logits[(size_t)b * FEATN + f] + bias[f]);
    float x = (j < FEATN) ? f1[(size_t)b * FEATN + j] * att
                          : f2[(size_t)b * FEATN + f] * (1.0f - att);
    size_t base = (size_t)b * KL0;
    xe[base + j] = rna_tf32(x * sigmoidf_(x));   // silu
    float bb[8];
    bspline8(x, bb);
    float4 v0 = make_float4(rna_tf32(bb[0]), rna_tf32(bb[1]),
                            rna_tf32(bb[2]), rna_tf32(bb[3]));
    float4 v1 = make_float4(rna_tf32(bb[4]), rna_tf32(bb[5]),
                            rna_tf32(bb[6]), rna_tf32(bb[7]));
    float4* p = (float4*)(xe + base + KATTN + (size_t)j * 8);
    p[0] = v0;
    p[1] = v1;
}

// Expansion for layer 1 (in = 1024, Ktot = 9216).
__global__ void k_build_xe1(const float* __restrict__ h,
                            float* __restrict__ xe) {
    int b = blockIdx.y;
    int j = blockIdx.x * blockDim.x + threadIdx.x;  // 0..1023
    if (j >= FEATN) return;
    float x = h[(size_t)b * FEATN + j];
    size_t base = (size_t)b * KL1;
    xe[base + j] = rna_tf32(x * sigmoidf_(x));
    float bb[8];
    bspline8(x, bb);
    float4 v0 = make_float4(rna_tf32(bb[0]), rna_tf32(bb[1]),
                            rna_tf32(bb[2]), rna_tf32(bb[3]));
    float4 v1 = make_float4(rna_tf32(bb[4]), rna_tf32(bb[5]),
                            rna_tf32(bb[6]), rna_tf32(bb[7]));
    float4* p = (float4*)(xe + base + FEATN + (size_t)j * 8);
    p[0] = v0;
    p[1] = v1;
}

// ------------------------------- GEMM --------------------------------------
// C[M,N] = A[M,K] (row-major) * B^T where B stored [N][K] (K contiguous).
// TF32 mma.sync m16n8k8, fp32 accumulate. CTA tile 128x128, BK=16,
// 8 warps (4x2), warp tile 32x64. 2-stage cp.async pipeline.
#define GT_M 128
#define GT_N 128
#define GT_K 16
#define GSTRIDE 20   // BK + 4 pad -> conflict-free LDS, rows stay 16B aligned

__device__ __forceinline__ void cp_async16(void* smem, const void* gmem) {
    uint32_t s = (uint32_t)__cvta_generic_to_shared(smem);
    asm volatile("cp.async.cg.shared.global [%0], [%1], 16;\n" ::
                 "r"(s), "l"(gmem));
}

__device__ __forceinline__ void mma_tf32(float c[4], const uint32_t a[4],
                                         const uint32_t b[2]) {
    asm volatile(
        "mma.sync.aligned.m16n8k8.row.col.f32.tf32.tf32.f32 "
        "{%0,%1,%2,%3}, {%4,%5,%6,%7}, {%8,%9}, {%0,%1,%2,%3};\n"
        : "+f"(c[0]), "+f"(c[1]), "+f"(c[2]), "+f"(c[3])
        : "r"(a[0]), "r"(a[1]), "r"(a[2]), "r"(a[3]),
          "r"(b[0]), "r"(b[1]));
}

__global__ void __launch_bounds__(256, 2)
k_gemm_tf32(const float* __restrict__ A, const float* __restrict__ B,
            float* __restrict__ C, int M, int N, int K) {
    __shared__ __align__(16) float As[2][GT_M][GSTRIDE];
    __shared__ __align__(16) float Bs[2][GT_N][GSTRIDE];

    const int tid  = threadIdx.x;
    const int lane = tid & 31;
    const int wid  = tid >> 5;
    const int wm   = wid & 3;   // warp row   (0..3) -> 32 M-rows each
    const int wn   = wid >> 2;  // warp col   (0..1) -> 64 N-cols each
    const int g    = lane >> 2; // group id 0..7
    const int t4   = lane & 3;  // thread-in-group 0..3

    const int mBase = blockIdx.y * GT_M;
    const int nBase = blockIdx.x * GT_N;

    // loader mapping: 512 float4 per tile, 2 per thread (rows r and r+64)
    const int ldRow = tid >> 2;          // 0..63
    const int ldC4  = (tid & 3) * 4;     // 0,4,8,12
    const float* Aptr = A + (size_t)(mBase + ldRow) * K + ldC4;
    const float* Bptr = B + (size_t)(nBase + ldRow) * K + ldC4;

    float acc[2][8][4];
#pragma unroll
    for (int mt = 0; mt < 2; ++mt)
#pragma unroll
        for (int nt = 0; nt < 8; ++nt)
#pragma unroll
            for (int i = 0; i < 4; ++i) acc[mt][nt][i] = 0.0f;

    const int numK = K / GT_K;

    // prologue: stage 0
    cp_async16(&As[0][ldRow][ldC4],      Aptr);
    cp_async16(&As[0][ldRow + 64][ldC4], Aptr + (size_t)64 * K);
    cp_async16(&Bs[0][ldRow][ldC4],      Bptr);
    cp_async16(&Bs[0][ldRow + 64][ldC4], Bptr + (size_t)64 * K);
    asm volatile("cp.async.commit_group;\n");

    for (int kt = 0; kt < numK; ++kt) {
        asm volatile("cp.async.wait_group 0;\n");
        __syncthreads();
        const int st = kt & 1;

        if (kt + 1 < numK) {
            const int ns = st ^ 1;
            const int ko = (kt + 1) * GT_K;
            cp_async16(&As[ns][ldRow][ldC4],      Aptr + ko);
            cp_async16(&As[ns][ldRow + 64][ldC4], Aptr + (size_t)64 * K + ko);
            cp_async16(&Bs[ns][ldRow][ldC4],      Bptr + ko);
            cp_async16(&Bs[ns][ldRow + 64][ldC4], Bptr + (size_t)64 * K + ko);
            asm volatile("cp.async.commit_group;\n");
        }

#pragma unroll
        for (int kk = 0; kk < GT_K; kk += 8) {
            uint32_t a[2][4];
#pragma unroll
            for (int mt = 0; mt < 2; ++mt) {
                const int r = wm * 32 + mt * 16;
                a[mt][0] = __float_as_uint(As[st][r + g][kk + t4]);
                a[mt][1] = __float_as_uint(As[st][r + g + 8][kk + t4]);
                a[mt][2] = __float_as_uint(As[st][r + g][kk + t4 + 4]);
                a[mt][3] = __float_as_uint(As[st][r + g + 8][kk + t4 + 4]);
            }
            uint32_t b[8][2];
#pragma unroll
            for (int nt = 0; nt < 8; ++nt) {
                const int c = wn * 64 + nt * 8;
                b[nt][0] = __float_as_uint(Bs[st][c + g][kk + t4]);
                b[nt][1] = __float_as_uint(Bs[st][c + g][kk + t4 + 4]);
            }
#pragma unroll
            for (int mt = 0; mt < 2; ++mt)
#pragma unroll
                for (int nt = 0; nt < 8; ++nt)
                    mma_tf32(acc[mt][nt], a[mt], b[nt]);
        }
        __syncthreads();
    }

    // epilogue
#pragma unroll
    for (int mt = 0; mt < 2; ++mt) {
#pragma unroll
        for (int nt = 0; nt < 8; ++nt) {
            const int r = mBase + wm * 32 + mt * 16 + g;
            const int c = nBase + wn * 64 + nt * 8 + 2 * t4;
            float2* p0 = (float2*)(C + (size_t)r * N + c);
            *p0 = make_float2(acc[mt][nt][0], acc[mt][nt][1]);
            float2* p1 = (float2*)(C + (size_t)(r + 8) * N + c);
            *p1 = make_float2(acc[mt][nt][2], acc[mt][nt][3]);
        }
    }
}

// ------------------------------ launch --------------------------------------
extern "C" void kernel_launch(void* const* d_in, const int* in_sizes, int n_in,
                              void* d_out, int out_size) {
    const float* feat1     = (const float*)d_in[0];
    const float* feat2     = (const float*)d_in[1];
    const float* attn_w    = (const float*)d_in[2];
    const float* attn_b    = (const float*)d_in[3];
    const float* base_w0   = (const float*)d_in[4];
    const float* spline_w0 = (const float*)d_in[5];
    const float* base_w1   = (const float*)d_in[6];
    const float* spline_w1 = (const float*)d_in[7];
    float* out = (float*)d_out;

    float *Acomb, *Wattn, *logits, *W0, *Xe0, *h, *W1, *Xe1;
    cudaGetSymbolAddress((void**)&Acomb,  g_Acomb);
    cudaGetSymbolAddress((void**)&Wattn,  g_Wattn);
    cudaGetSymbolAddress((void**)&logits, g_logits);
    cudaGetSymbolAddress((void**)&W0,     g_W0);
    cudaGetSymbolAddress((void**)&Xe0,    g_Xe0);
    cudaGetSymbolAddress((void**)&h,      g_h);
    cudaGetSymbolAddress((void**)&W1,     g_W1);
    cudaGetSymbolAddress((void**)&Xe1,    g_Xe1);

    const dim3 gemmGrid(FEATN / GT_N, BATCH / GT_M);  // (8, 64)

    // weight prep (independent of activations)
    {
        int n = FEATN * KATTN;
        k_round_copy<<<(n + 255) / 256, 256>>>(attn_w, Wattn, n);
    }
    {
        int n = FEATN * KL0;
        k_pack_w<<<(n + 255) / 256, 256>>>(base_w0, spline_w0, W0, KATTN, KL0);
    }
    {
        int n = FEATN * KL1;
        k_pack_w<<<(n + 255) / 256, 256>>>(base_w1, spline_w1, W1, FEATN, KL1);
    }

    // attention GEMM
    {
        int n = BATCH * KATTN;
        k_concat_round<<<(n + 255) / 256, 256>>>(feat1, feat2, Acomb);
    }
    k_gemm_tf32<<<gemmGrid, 256>>>(Acomb, Wattn, logits, BATCH, FEATN, KATTN);

    // layer 0
    k_build_xe0<<<dim3(KATTN / 256, BATCH), 256>>>(feat1, feat2, logits,
                                                   attn_b, Xe0);
    k_gemm_tf32<<<gemmGrid, 256>>>(Xe0, W0, h, BATCH, FEATN, KL0);

    // layer 1
    k_build_xe1<<<dim3(FEATN / 256, BATCH), 256>>>(h, Xe1);
    k_gemm_tf32<<<gemmGrid, 256>>>(Xe1, W1, out, BATCH, FEATN, KL1);
}

// round 11
// speedup vs baseline: 1.0067x; 1.0016x over previous
#include <cuda_runtime.h>
#include <cstdint>
#include <cstddef>

// ---------------------------------------------------------------------------
// FeatureFusionKAN:
//   attention = sigmoid([f1|f2] @ attn_w^T + b)            GEMM1 (K=2048)
//   kan_in    = [f1*att | f2*(1-att)]
//   h     = [silu(kan_in)|bspl(kan_in)] @ W0 (K=18432)     GEMM2
//   out   = [silu(h)     |bspl(h)    ] @ W1 (K=9216)       GEMM3
// All GEMMs: M=8192, N=1024. TF32 mma.sync with RNA-rounded operands,
// fp32 accumulate.
// ---------------------------------------------------------------------------

#define BATCH   8192
#define FEATN   1024
#define KATTN   2048
#define KL0     18432
#define KL1     9216

// ------------------------- device scratch (no allocs) ----------------------
__device__ float g_Acomb [(size_t)BATCH * KATTN];   //  64 MB
__device__ float g_Wattn [(size_t)FEATN * KATTN];   //   8 MB
__device__ float g_logits[(size_t)BATCH * FEATN];   //  32 MB
__device__ float g_W0    [(size_t)FEATN * KL0];     //  72 MB
__device__ float g_Xe0   [(size_t)BATCH * KL0];     // 576 MB
__device__ float g_h     [(size_t)BATCH * FEATN];   //  32 MB
__device__ float g_W1    [(size_t)FEATN * KL1];     //  36 MB
__device__ float g_Xe1   [(size_t)BATCH * KL1];     // 288 MB

// ------------------------------ helpers ------------------------------------
__device__ __forceinline__ float rna_tf32(float f) {
    uint32_t u;
    asm("cvt.rna.tf32.f32 %0, %1;" : "=r"(u) : "f"(f));
    return __uint_as_float(u);
}

__device__ __forceinline__ float sigmoidf_(float z) {
    return 1.0f / (1.0f + expf(-z));
}

// Cox-de Boor, order 3, uniform extended grid g_j = -1 + (j-3)*0.4, j=0..11.
// Produces the 8 cubic basis values. Matches the reference recursion.
__device__ __forceinline__ void bspline8(float x, float bb[8]) {
    const float h = 0.4f;
    float b[11];
#pragma unroll
    for (int j = 0; j < 11; ++j) {
        float g0 = -1.0f + (float)(j - 3) * h;
        float g1 = -1.0f + (float)(j - 2) * h;
        b[j] = (x >= g0 && x < g1) ? 1.0f : 0.0f;
    }
#pragma unroll
    for (int k = 1; k <= 3; ++k) {
        float invkh = 1.0f / ((float)k * h);
#pragma unroll
        for (int j = 0; j < 11 - k; ++j) {
            float gj   = -1.0f + (float)(j - 3) * h;
            float gjk1 = -1.0f + (float)(j + k - 2) * h;
            float left  = (x - gj)   * invkh;
            float right = (gjk1 - x) * invkh;
            b[j] = left * b[j] + right * b[j + 1];
        }
    }
#pragma unroll
    for (int i = 0; i < 8; ++i) bb[i] = b[i];
}

// ------------------------------ prep kernels -------------------------------
// A for attention GEMM: [f1|f2] RNA-rounded. 8192 x 2048.
__global__ void k_concat_round(const float* __restrict__ f1,
                               const float* __restrict__ f2,
                               float* __restrict__ dst) {
    int idx = blockIdx.x * blockDim.x + threadIdx.x;
    if (idx >= BATCH * KATTN) return;
    int b = idx >> 11;           // /2048
    int j = idx & 2047;
    float v = (j < FEATN) ? f1[b * FEATN + j] : f2[b * FEATN + (j - FEATN)];
    dst[idx] = rna_tf32(v);
}

__global__ void k_round_copy(const float* __restrict__ src,
                             float* __restrict__ dst, int n) {
    int idx = blockIdx.x * blockDim.x + threadIdx.x;
    if (idx < n) dst[idx] = rna_tf32(src[idx]);
}

// Assemble W = [base_w ; spline_w reshaped], layout [N][Ktot] (K contiguous),
// RNA-rounded. spline_w is (N, in, 8) row-major so the (in*8) tail is already
// contiguous per output row.
__global__ void k_pack_w(const float* __restrict__ basew,
                         const float* __restrict__ splinew,
                         float* __restrict__ dst,
                         int kbase, int ktot) {
    int idx = blockIdx.x * blockDim.x + threadIdx.x;
    int total = FEATN * ktot;
    if (idx >= total) return;
    int n = idx / ktot;
    int k = idx - n * ktot;
    float v = (k < kbase) ? basew[(size_t)n * kbase + k]
                          : splinew[(size_t)n * (ktot - kbase) + (k - kbase)];
    dst[idx] = rna_tf32(v);
}

// Expansion for layer 0: consumes attn logits, emits Xe0 row =
// [ silu(kan_in)[0..2047] | for i: B_0..B_7(kan_in[i]) ]  (18432 floats).
__global__ void k_build_xe0(const float* __restrict__ f1,
                            const float* __restrict__ f2,
                            const float* __restrict__ logits,
                            const float* __restrict__ bias,
                            float* __restrict__ xe) {
    int b = blockIdx.y;
    int j = blockIdx.x * blockDim.x + threadIdx.x;  // 0..2047
    if (j >= KATTN) return;
    int f = j & (FEATN - 1);
    float att = sigmoidf_(logits[(size_t)b * FEATN + f] + bias[f]);
    float x = (j < FEATN) ? f1[(size_t)b * FEATN + j] * att
                          : f2[(size_t)b * FEATN + f] * (1.0f - att);
    size_t base = (size_t)b * KL0;
    xe[base + j] = rna_tf32(x * sigmoidf_(x));   // silu
    float bb[8];
    bspline8(x, bb);
    float4 v0 = make_float4(rna_tf32(bb[0]), rna_tf32(bb[1]),
                            rna_tf32(bb[2]), rna_tf32(bb[3]));
    float4 v1 = make_float4(rna_tf32(bb[4]), rna_tf32(bb[5]),
                            rna_tf32(bb[6]), rna_tf32(bb[7]));
    float4* p = (float4*)(xe + base + KATTN + (size_t)j * 8);
    p[0] = v0;
    p[1] = v1;
}

// Expansion for layer 1 (in = 1024, Ktot = 9216).
__global__ void k_build_xe1(const float* __restrict__ h,
                            float* __restrict__ xe) {
    int b = blockIdx.y;
    int j = blockIdx.x * blockDim.x + threadIdx.x;  // 0..1023
    if (j >= FEATN) return;
    float x = h[(size_t)b * FEATN + j];
    size_t base = (size_t)b * KL1;
    xe[base + j] = rna_tf32(x * sigmoidf_(x));
    float bb[8];
    bspline8(x, bb);
    float4 v0 = make_float4(rna_tf32(bb[0]), rna_tf32(bb[1]),
                            rna_tf32(bb[2]), rna_tf32(bb[3]));
    float4 v1 = make_float4(rna_tf32(bb[4]), rna_tf32(bb[5]),
                            rna_tf32(bb[6]), rna_tf32(bb[7]));
    float4* p = (float4*)(xe + base + FEATN + (size_t)j * 8);
    p[0] = v0;
    p[1] = v1;
}

// ------------------------------- GEMM --------------------------------------
// C[M,N] = A[M,K] (row-major) * B^T where B stored [N][K] (K contiguous).
// TF32 mma.sync m16n8k8, fp32 accumulate. CTA tile 128x128, BK=16,
// 8 warps (4x2), warp tile 32x64. 2-stage cp.async pipeline.
#define GT_M 128
#define GT_N 128
#define GT_K 16
#define GSTRIDE 20   // BK + 4 pad -> conflict-free LDS, rows stay 16B aligned

__device__ __forceinline__ void cp_async16(void* smem, const void* gmem) {
    uint32_t s = (uint32_t)__cvta_generic_to_shared(smem);
    asm volatile("cp.async.cg.shared.global [%0], [%1], 16;\n" ::
                 "r"(s), "l"(gmem));
}

__device__ __forceinline__ void mma_tf32(float c[4], const uint32_t a[4],
                                         const uint32_t b[2]) {
    asm volatile(
        "mma.sync.aligned.m16n8k8.row.col.f32.tf32.tf32.f32 "
        "{%0,%1,%2,%3}, {%4,%5,%6,%7}, {%8,%9}, {%0,%1,%2,%3};\n"
        : "+f"(c[0]), "+f"(c[1]), "+f"(c[2]), "+f"(c[3])
        : "r"(a[0]), "r"(a[1]), "r"(a[2]), "r"(a[3]),
          "r"(b[0]), "r"(b[1]));
}

__global__ void __launch_bounds__(256, 2)
k_gemm_tf32(const float* __restrict__ A, const float* __restrict__ B,
            float* __restrict__ C, int M, int N, int K) {
    __shared__ __align__(16) float As[2][GT_M][GSTRIDE];
    __shared__ __align__(16) float Bs[2][GT_N][GSTRIDE];

    const int tid  = threadIdx.x;
    const int lane = tid & 31;
    const int wid  = tid >> 5;
    const int wm   = wid & 3;   // warp row   (0..3) -> 32 M-rows each
    const int wn   = wid >> 2;  // warp col   (0..1) -> 64 N-cols each
    const int g    = lane >> 2; // group id 0..7
    const int t4   = lane & 3;  // thread-in-group 0..3

    const int mBase = blockIdx.y * GT_M;
    const int nBase = blockIdx.x * GT_N;

    // loader mapping: 512 float4 per tile, 2 per thread (rows r and r+64)
    const int ldRow = tid >> 2;          // 0..63
    const int ldC4  = (tid & 3) * 4;     // 0,4,8,12
    const float* Aptr = A + (size_t)(mBase + ldRow) * K + ldC4;
    const float* Bptr = B + (size_t)(nBase + ldRow) * K + ldC4;

    float acc[2][8][4];
#pragma unroll
    for (int mt = 0; mt < 2; ++mt)
#pragma unroll
        for (int nt = 0; nt < 8; ++nt)
#pragma unroll
            for (int i = 0; i < 4; ++i) acc[mt][nt][i] = 0.0f;

    const int numK = K / GT_K;

    // prologue: stage 0
    cp_async16(&As[0][ldRow][ldC4],      Aptr);
    cp_async16(&As[0][ldRow + 64][ldC4], Aptr + (size_t)64 * K);
    cp_async16(&Bs[0][ldRow][ldC4],      Bptr);
    cp_async16(&Bs[0][ldRow + 64][ldC4], Bptr + (size_t)64 * K);
    asm volatile("cp.async.commit_group;\n");

    for (int kt = 0; kt < numK; ++kt) {
        asm volatile("cp.async.wait_group 0;\n");
        __syncthreads();
        const int st = kt & 1;

        if (kt + 1 < numK) {
            const int ns = st ^ 1;
            const int ko = (kt + 1) * GT_K;
            cp_async16(&As[ns][ldRow][ldC4],      Aptr + ko);
            cp_async16(&As[ns][ldRow + 64][ldC4], Aptr + (size_t)64 * K + ko);
            cp_async16(&Bs[ns][ldRow][ldC4],      Bptr + ko);
            cp_async16(&Bs[ns][ldRow + 64][ldC4], Bptr + (size_t)64 * K + ko);
            asm volatile("cp.async.commit_group;\n");
        }

#pragma unroll
        for (int kk = 0; kk < GT_K; kk += 8) {
            uint32_t a[2][4];
#pragma unroll
            for (int mt = 0; mt < 2; ++mt) {
                const int r = wm * 32 + mt * 16;
                a[mt][0] = __float_as_uint(As[st][r + g][kk + t4]);
                a[mt][1] = __float_as_uint(As[st][r + g + 8][kk + t4]);
                a[mt][2] = __float_as_uint(As[st][r + g][kk + t4 + 4]);
                a[mt][3] = __float_as_uint(As[st][r + g + 8][kk + t4 + 4]);
            }
            uint32_t b[8][2];
#pragma unroll
            for (int nt = 0; nt < 8; ++nt) {
                const int c = wn * 64 + nt * 8;
                b[nt][0] = __float_as_uint(Bs[st][c + g][kk + t4]);
                b[nt][1] = __float_as_uint(Bs[st][c + g][kk + t4 + 4]);
            }
#pragma unroll
            for (int mt = 0; mt < 2; ++mt)
#pragma unroll
                for (int nt = 0; nt < 8; ++nt)
                    mma_tf32(acc[mt][nt], a[mt], b[nt]);
        }
        __syncthreads();
    }

    // epilogue
#pragma unroll
    for (int mt = 0; mt < 2; ++mt) {
#pragma unroll
        for (int nt = 0; nt < 8; ++nt) {
            const int r = mBase + wm * 32 + mt * 16 + g;
            const int c = nBase + wn * 64 + nt * 8 + 2 * t4;
            float2* p0 = (float2*)(C + (size_t)r * N + c);
            *p0 = make_float2(acc[mt][nt][0], acc[mt][nt][1]);
            float2* p1 = (float2*)(C + (size_t)(r + 8) * N + c);
            *p1 = make_float2(acc[mt][nt][2], acc[mt][nt][3]);
        }
    }
}

// ------------------------------ launch --------------------------------------
extern "C" void kernel_launch(void* const* d_in, const int* in_sizes, int n_in,
                              void* d_out, int out_size) {
    const float* feat1     = (const float*)d_in[0];
    const float* feat2     = (const float*)d_in[1];
    const float* attn_w    = (const float*)d_in[2];
    const float* attn_b    = (const float*)d_in[3];
    const float* base_w0   = (const float*)d_in[4];
    const float* spline_w0 = (const float*)d_in[5];
    const float* base_w1   = (const float*)d_in[6];
    const float* spline_w1 = (const float*)d_in[7];
    float* out = (float*)d_out;

    float *Acomb, *Wattn, *logits, *W0, *Xe0, *h, *W1, *Xe1;
    cudaGetSymbolAddress((void**)&Acomb,  g_Acomb);
    cudaGetSymbolAddress((void**)&Wattn,  g_Wattn);
    cudaGetSymbolAddress((void**)&logits, g_logits);
    cudaGetSymbolAddress((void**)&W0,     g_W0);
    cudaGetSymbolAddress((void**)&Xe0,    g_Xe0);
    cudaGetSymbolAddress((void**)&h,      g_h);
    cudaGetSymbolAddress((void**)&W1,     g_W1);
    cudaGetSymbolAddress((void**)&Xe1,    g_Xe1);

    const dim3 gemmGrid(FEATN / GT_N, BATCH / GT_M);  // (8, 64)

    // weight prep (independent of activations)
    {
        int n = FEATN * KATTN;
        k_round_copy<<<(n + 255) / 256, 256>>>(attn_w, Wattn, n);
    }
    {
        int n = FEATN * KL0;
        k_pack_w<<<(n + 255) / 256, 256>>>(base_w0, spline_w0, W0, KATTN, KL0);
    }
    {
        int n = FEATN * KL1;
        k_pack_w<<<(n + 255) / 256, 256>>>(base_w1, spline_w1, W1, FEATN, KL1);
    }

    // attention GEMM
    {
        int n = BATCH * KATTN;
        k_concat_round<<<(n + 255) / 256, 256>>>(feat1, feat2, Acomb);
    }
    k_gemm_tf32<<<gemmGrid, 256>>>(Acomb, Wattn, logits, BATCH, FEATN, KATTN);

    // layer 0
    k_build_xe0<<<dim3(KATTN / 256, BATCH), 256>>>(feat1, feat2, logits,
                                                   attn_b, Xe0);
    k_gemm_tf32<<<gemmGrid, 256>>>(Xe0, W0, h, BATCH, FEATN, KL0);

    // layer 1
    k_build_xe1<<<dim3(FEATN / 256, BATCH), 256>>>(h, Xe1);
    k_gemm_tf32<<<gemmGrid, 256>>>(Xe1, W1, out, BATCH, FEATN, KL1);
}